// round 11
// baseline (speedup 1.0000x reference)
#include <cuda_runtime.h>
#include <cstdint>
#include <math.h>

#define H    8192      // DIM_HIDDEN
#define S    4096      // DIM_SOL (steps)
#define CTX  4096      // DIM_CONTEXT
#define CSZ  8         // cluster size
#define NWW  8         // worker warps per CTA (wids 3..10)
#define WTH  256       // worker threads per CTA
#define TPB  352       // sender(0) + decider(1) + logp(2) + 8 workers
#define RDEP 4         // ring depth

// ---------------- device scratch (static, no allocs) ----------------
__device__ float  g_Wt[(size_t)S * H];   // transposed W[:, CTX:]
__device__ float  g_Kt[(size_t)S * H];   // exp(-g_Wt)
__device__ float  g_a0[H];               // a0 = c + W[:, :CTX] @ context
__device__ float2 g_thr2[S];             // (t_hi, t_lo) two-float logit(u_i)

// ---------------- helpers ----------------
__device__ __forceinline__ float sigmoidf_fast(float x) {
    return __fdividef(1.0f, 1.0f + __expf(-x));
}
__device__ __forceinline__ float softplusf(float y) {
    float t = fabsf(y);
    float r = log1pf(__expf(-t));
    return (y > 0.f) ? (y + r) : r;
}
__device__ __forceinline__ unsigned cluster_rank() {
    unsigned r; asm("mov.u32 %0, %%cluster_ctarank;" : "=r"(r)); return r;
}
__device__ __forceinline__ uint32_t smem_u32(const void* p) {
    return (uint32_t)__cvta_generic_to_shared(p);
}
__device__ __forceinline__ uint32_t mapa_addr(uint32_t laddr, unsigned rank) {
    uint32_t raddr;
    asm("mapa.shared::cluster.u32 %0, %1, %2;" : "=r"(raddr) : "r"(laddr), "r"(rank));
    return raddr;
}
__device__ __forceinline__ void remote_store64(uint32_t laddr, unsigned rank, unsigned long long v) {
    uint32_t raddr = mapa_addr(laddr, rank);
    asm volatile("st.relaxed.cluster.shared::cluster.b64 [%0], %1;" :: "r"(raddr), "l"(v) : "memory");
}
__device__ __forceinline__ unsigned long long remote_ld64(uint32_t raddr) {
    unsigned long long v;
    asm volatile("ld.relaxed.cluster.shared::cluster.b64 %0, [%1];" : "=l"(v) : "r"(raddr) : "memory");
    return v;
}
__device__ __forceinline__ void cluster_barrier() {
    asm volatile("barrier.cluster.arrive.aligned;" ::: "memory");
    asm volatile("barrier.cluster.wait.aligned;"   ::: "memory");
}
__device__ __forceinline__ uint4 lds128v(const void* p) {
    uint4 r;
    asm volatile("ld.volatile.shared.v4.b32 {%0,%1,%2,%3}, [%4];"
                 : "=r"(r.x), "=r"(r.y), "=r"(r.z), "=r"(r.w) : "r"(smem_u32(p)));
    return r;
}
__device__ __forceinline__ void sts128(void* p, unsigned a, unsigned b, unsigned c, unsigned d) {
    asm volatile("st.shared.v4.b32 [%0], {%1,%2,%3,%4};"
                 :: "r"(smem_u32(p)), "r"(a), "r"(b), "r"(c), "r"(d) : "memory");
}
// interleaved quad warp-sum (workers only; 3T of slack)
__device__ __forceinline__ void bfly4(float& a, float& b, float& c, float& d) {
    #pragma unroll
    for (int o = 16; o > 0; o >>= 1) {
        a += __shfl_xor_sync(0xffffffffu, a, o);
        b += __shfl_xor_sync(0xffffffffu, b, o);
        c += __shfl_xor_sync(0xffffffffu, c, o);
        d += __shfl_xor_sync(0xffffffffu, d, o);
    }
}
__device__ __forceinline__ bool thr_cmp(float x, float2 t) {
    return (x > t.x) || ((x == t.x) && (t.y < 0.f));
}

// ---------------- init kernels ----------------
__global__ void gemv_kernel(const float* __restrict__ W,
                            const float* __restrict__ ctxv,
                            const float* __restrict__ c) {
    __shared__ float sred[256];
    int r = blockIdx.x;
    const float* row = W + (size_t)r * (CTX + S);
    float acc = 0.f;
    for (int k = threadIdx.x; k < CTX; k += 256)
        acc += row[k] * ctxv[k];
    sred[threadIdx.x] = acc;
    __syncthreads();
    for (int off = 128; off > 0; off >>= 1) {
        if (threadIdx.x < off) sred[threadIdx.x] += sred[threadIdx.x + off];
        __syncthreads();
    }
    if (threadIdx.x == 0) g_a0[r] = c[r] + sred[0];
}

// transpose W[:, CTX:] and emit both Wt and Kt = exp(-Wt) in one pass
__global__ void transpose_kernel(const float* __restrict__ W) {
    __shared__ float tile[32][33];
    int i0 = blockIdx.x * 32;
    int j0 = blockIdx.y * 32;
    int tx = threadIdx.x;
    #pragma unroll
    for (int t = 0; t < 4; t++) {
        int ty = threadIdx.y + t * 8;
        tile[ty][tx] = W[(size_t)(j0 + ty) * (CTX + S) + CTX + i0 + tx];
    }
    __syncthreads();
    #pragma unroll
    for (int t = 0; t < 4; t++) {
        int ty = threadIdx.y + t * 8;
        float w = tile[tx][ty];
        size_t idx = (size_t)(i0 + ty) * H + j0 + tx;
        g_Wt[idx] = w;
        g_Kt[idx] = __expf(-w);
    }
}

__global__ void thr_kernel(const float* __restrict__ u) {
    int i = blockIdx.x * 256 + threadIdx.x;
    if (i < S) {
        double ud = (double)u[i];
        double t  = log(ud / (1.0 - ud));
        float hi  = (float)t;
        float lo  = (float)(t - (double)hi);
        g_thr2[i] = make_float2(hi, lo);
    }
}

// ---------------- main sequential kernel: 8-CTA cluster ----------------
// wpq[r][w][c] = {tag, z_c0, z_c1, tag} per worker warp w, branch c = s_{p-2}
// pub[r][0/1]  = locally-published {tag|F0} / {tag|F1}; peers PULL via DSMEM loads
__global__ void __cluster_dims__(CSZ, 1, 1) __launch_bounds__(TPB, 1)
nade_kernel(const float* __restrict__ V,
            const float* __restrict__ b,
            float* __restrict__ out,
            int out_size) {
    __shared__ __align__(16) uint4              wpq[RDEP][NWW][2];
    __shared__ __align__(16) unsigned long long pub[RDEP][2];
    __shared__ unsigned int       dec[RDEP];
    __shared__ unsigned long long xw[S];

    const unsigned rank = cluster_rank();
    const int tid  = threadIdx.x;
    const int wid  = tid >> 5;
    const int lane = tid & 31;
    const unsigned FULL = 0xffffffffu;

    for (int k = tid; k < RDEP * NWW * 2; k += TPB)
        ((uint4*)wpq)[k] = make_uint4(0xFFFFFFFFu, 0, 0, 0xFFFFFFFFu);
    if (tid < RDEP * 2)
        ((unsigned long long*)pub)[tid] = 0xFFFFFFFF00000000ULL;
    if (tid < RDEP) dec[tid] = 0xFFFFFFFFu;
    for (int k = tid; k < S; k += TPB)
        xw[k] = 0xFFFFFFFF00000000ULL;
    __syncthreads();
    cluster_barrier();   // all pub arrays initialized before any peer reads them

    volatile unsigned int*       decv = dec;
    volatile unsigned long long* xwv  = xw;

    if (wid >= 3) {
        // ================= worker warps (wids 3..10) =================
        const int w    = wid - 3;
        const int wtid = tid - 96;                       // 0..255
        const int j0   = (int)rank * (WTH * 4) + wtid * 4;

        float a[4];
        float s00[4], s01[4], s10[4], s11[4];            // sig quad (current step)
        float4 w8[8], k8[8], v8[8];                      // register rings

        auto publish = [&](int p, float z00, float z01, float z10, float z11) {
            bfly4(z00, z01, z10, z11);
            if (lane == 0) {
                unsigned tg = (unsigned)p;
                const int r = p & (RDEP - 1);
                sts128(&wpq[r][w][0], tg, __float_as_uint(z00), __float_as_uint(z01), tg);
                sts128(&wpq[r][w][1], tg, __float_as_uint(z10), __float_as_uint(z11), tg);
            }
        };

        // ---- prologue: quads 0,1,2; state for iter 3 ----
        {
            float4 av = *(const float4*)&g_a0[j0];
            float4 w0 = *(const float4*)&g_Wt[j0];
            float4 w1 = *(const float4*)&g_Wt[(size_t)1 * H + j0];
            float4 v0 = *(const float4*)&V[j0];
            float4 v1 = *(const float4*)&V[(size_t)1 * H + j0];
            float4 v2 = *(const float4*)&V[(size_t)2 * H + j0];
            const float ava[4] = {av.x, av.y, av.z, av.w};
            const float w0a[4] = {w0.x, w0.y, w0.z, w0.w};
            const float w1a[4] = {w1.x, w1.y, w1.z, w1.w};
            const float v0a[4] = {v0.x, v0.y, v0.z, v0.w};
            const float v1a[4] = {v1.x, v1.y, v1.z, v1.w};
            const float v2a[4] = {v2.x, v2.y, v2.z, v2.w};

            float z = 0.f, zA = 0.f, zB = 0.f;
            float q00 = 0.f, q01 = 0.f, q10 = 0.f, q11 = 0.f;
            #pragma unroll
            for (int e = 0; e < 4; e++) {
                a[e] = ava[e];
                float h0 = sigmoidf_fast(a[e]);
                s00[e] = h0;
                s10[e] = sigmoidf_fast(a[e] + w0a[e]);
                s01[e] = sigmoidf_fast(a[e] + w1a[e]);
                s11[e] = sigmoidf_fast(a[e] + w0a[e] + w1a[e]);
                z  = fmaf(v0a[e], h0, z);
                zA = fmaf(v1a[e], h0, zA);
                zB = fmaf(v1a[e], s10[e], zB);
                q00 = fmaf(v2a[e], s00[e], q00);
                q01 = fmaf(v2a[e], s01[e], q01);
                q10 = fmaf(v2a[e], s10[e], q10);
                q11 = fmaf(v2a[e], s11[e], q11);
            }
            publish(0, z,  z,  z,  z);
            publish(1, zA, zB, zA, zB);
            publish(2, q00, q01, q10, q11);

            #pragma unroll
            for (int rI = 0; rI < 7; rI++) {
                w8[rI] = *(const float4*)&g_Wt[(size_t)rI * H + j0];
                k8[rI] = *(const float4*)&g_Kt[(size_t)rI * H + j0];
                v8[rI] = *(const float4*)&V[(size_t)rI * H + j0];
            }
        }

        // ---- main loop ----
        #pragma unroll 8
        for (int p = 3; p < 3 + 4096; p++) {
            int pf = (p + 4 < S) ? p + 4 : S - 1;
            w8[(p + 4) & 7] = *(const float4*)&g_Wt[(size_t)pf * H + j0];
            k8[(p + 4) & 7] = *(const float4*)&g_Kt[(size_t)pf * H + j0];
            v8[(p + 4) & 7] = *(const float4*)&V[(size_t)pf * H + j0];

            // pre-dec: xpre = exp(-(A_{p-4} + W_{p-1}))
            float4 wm1 = w8[(p - 1) & 7];
            float xpre[4];
            xpre[0] = __expf(-(a[0] + wm1.x));
            xpre[1] = __expf(-(a[1] + wm1.y));
            xpre[2] = __expf(-(a[2] + wm1.z));
            xpre[3] = __expf(-(a[3] + wm1.w));

            unsigned d;
            do { d = decv[(p - 3) & (RDEP - 1)]; } while ((d >> 1) != (unsigned)(p - 3));
            const bool  s  = (d & 1);
            const float sm = (float)(d & 1);

            float4 wm3 = w8[(p - 3) & 7];
            float4 km3 = k8[(p - 3) & 7];
            float4 km2 = k8[(p - 2) & 7];
            float4 vp  = v8[p & 7];
            const float wm3a[4] = {wm3.x, wm3.y, wm3.z, wm3.w};
            const float km3a[4] = {km3.x, km3.y, km3.z, km3.w};
            const float km2a[4] = {km2.x, km2.y, km2.z, km2.w};
            const float vpa[4]  = {vp.x,  vp.y,  vp.z,  vp.w};

            float z00 = 0.f, z01 = 0.f, z10 = 0.f, z11 = 0.f;
            #pragma unroll
            for (int e = 0; e < 4; e++) {
                a[e] = fmaf(sm, wm3a[e], a[e]);
                float Xi  = s ? xpre[e] * km3a[e] : xpre[e];
                float n00 = s ? s10[e] : s00[e];
                float n10 = s ? s11[e] : s01[e];
                float n01 = __fdividef(1.f, 1.f + Xi);
                float n11 = __fdividef(1.f, 1.f + Xi * km2a[e]);
                z00 = fmaf(vpa[e], n00, z00);
                z01 = fmaf(vpa[e], n01, z01);
                z10 = fmaf(vpa[e], n10, z10);
                z11 = fmaf(vpa[e], n11, z11);
                s00[e] = n00; s01[e] = n01; s10[e] = n10; s11[e] = n11;
            }
            if (p < S) publish(p, z00, z01, z10, z11);
        }
    } else if (wid == 0) {
        // ================= sender warp: aggregate + LOCAL publish =================
        for (int p = 0; p < S; p++) {
            const unsigned want = (unsigned)p;
            const int r = p & (RDEP - 1);
            uint4 u0[NWW], u1[NWW];
            for (;;) {
                bool ok = true;
                #pragma unroll
                for (int w = 0; w < NWW; w++) {
                    u0[w] = lds128v(&wpq[r][w][0]);
                    u1[w] = lds128v(&wpq[r][w][1]);
                    ok &= (u0[w].x == want) & (u0[w].w == want)
                        & (u1[w].x == want) & (u1[w].w == want);
                }
                if (ok) break;
            }
            unsigned c = 0;
            if (p >= 2) {
                unsigned d;
                do { d = decv[(p - 2) & (RDEP - 1)]; } while ((d >> 1) != (unsigned)(p - 2));
                c = d & 1;
            }
            float f0[NWW], f1[NWW];
            #pragma unroll
            for (int w = 0; w < NWW; w++) {
                f0[w] = __uint_as_float(c ? u1[w].y : u0[w].y);
                f1[w] = __uint_as_float(c ? u1[w].z : u0[w].z);
            }
            float F0 = ((f0[0] + f0[1]) + (f0[2] + f0[3])) + ((f0[4] + f0[5]) + (f0[6] + f0[7]));
            float F1 = ((f1[0] + f1[1]) + (f1[2] + f1[3])) + ((f1[4] + f1[5]) + (f1[6] + f1[7]));
            if (lane < 2) {
                float val = lane ? F1 : F0;
                unsigned long long pk =
                    ((unsigned long long)want << 32) | (unsigned long long)__float_as_uint(val);
                // publish into OWN smem via DSMEM local path (cluster-scope visible)
                remote_store64(smem_u32(&pub[r][lane]), rank, pk);
            }
        }
    } else if (wid == 1) {
        // ================= decider warp: PULL peers' pub via DSMEM loads =================
        float  bc = b[0],      bn = b[1];
        float2 tc = g_thr2[0], tn = g_thr2[1];
        unsigned sprev = 0;
        const bool xwriter = (rank == 0 && lane == 0);

        // lane<16: cta = lane>>1, half = lane&1; precompute remote addrs per ring slot
        uint32_t raddr[RDEP];
        if (lane < 16) {
            #pragma unroll
            for (int r = 0; r < RDEP; r++)
                raddr[r] = mapa_addr(smem_u32(&pub[r][lane & 1]), (unsigned)(lane >> 1));
        }

        unsigned long long v = 0xFFFFFFFF00000000ULL;
        if (lane < 16) v = remote_ld64(raddr[0]);

        for (int i = 0; i < S; i++) {
            const unsigned want = (unsigned)i;
            const int r = i & (RDEP - 1);

            while (!__all_sync(FULL, (lane >= 16) || ((unsigned)(v >> 32) == want))) {
                if (lane < 16) v = remote_ld64(raddr[r]);
            }
            // pipeline: launch next step's loads while we reduce/decide
            unsigned long long vn = 0xFFFFFFFF00000000ULL;
            if ((i + 1 < S) && lane < 16) vn = remote_ld64(raddr[(i + 1) & (RDEP - 1)]);

            // reduce across CTAs within each half (offsets 2,4,8 keep parity)
            float f = (lane < 16) ? __uint_as_float((unsigned)v) : 0.f;
            f += __shfl_xor_sync(FULL, f, 2);
            f += __shfl_xor_sync(FULL, f, 4);
            f += __shfl_xor_sync(FULL, f, 8);
            float other = __shfl_xor_sync(FULL, f, 1);
            float D0 = (lane & 1) ? other : f;
            float D1 = (lane & 1) ? f : other;

            float x = bc + (sprev ? D1 : D0);
            bool  s = thr_cmp(x, tc);
            sprev = (unsigned)s;

            if (lane == 0)
                decv[r] = (want << 1) | (unsigned)s;
            if (xwriter)
                xwv[i] = ((unsigned long long)want << 32) |
                         (unsigned long long)__float_as_uint(x);

            int ip = (i + 2 < S) ? i + 2 : S - 1;
            float bf = b[ip]; float2 tf = g_thr2[ip];
            bc = bn; bn = bf; tc = tn; tn = tf;
            v = vn;
        }
    } else {
        // ================= logp/output warp (wid 2; rank 0, lane 0) =================
        if (rank == 0 && lane == 0) {
            float2 tc = g_thr2[0], tn = g_thr2[1];
            double lp = 0.0;
            for (int i = 0; i < S; i++) {
                unsigned long long xv;
                do { xv = xwv[i]; } while ((unsigned)(xv >> 32) != (unsigned)i);
                float x = __uint_as_float((unsigned)xv);
                bool  s = thr_cmp(x, tc);
                out[i] = s ? 1.0f : 0.0f;
                if (i < S - 2)
                    lp -= (double)(s ? softplusf(-x) : softplusf(x));
                int ip = (i + 2 < S) ? i + 2 : S - 1;
                float2 tf = g_thr2[ip];
                tc = tn; tn = tf;
            }
            out[S] = (float)lp;
            for (int k = S + 1; k < out_size; k++) out[k] = 0.f;
        }
    }

    cluster_barrier();   // no CTA exits while peers may still read its pub
}

// ---------------- launch ----------------
extern "C" void kernel_launch(void* const* d_in, const int* in_sizes, int n_in,
                              void* d_out, int out_size) {
    const float* ctxv = nullptr;
    const float* u    = nullptr;
    const float* W    = nullptr;
    const float* V    = nullptr;
    const float* b    = nullptr;
    const float* c    = nullptr;

    const int szW = (CTX + S) * H;   // 67108864
    const int szV = S * H;           // 33554432
    int n4seen = 0;
    for (int idx = 0; idx < n_in; idx++) {
        int sz = in_sizes[idx];
        const float* p = (const float*)d_in[idx];
        if (sz == szW)       W = p;
        else if (sz == szV)  V = p;
        else if (sz == H)    c = p;
        else if (sz == S) {
            if      (n4seen == 0) ctxv = p;
            else if (n4seen == 1) u    = p;
            else                  b    = p;
            n4seen++;
        }
    }
    if (!ctxv) ctxv = (const float*)d_in[0];
    if (!u)    u    = (const float*)d_in[1];
    if (!W)    W    = (const float*)d_in[2];
    if (!V)    V    = (const float*)d_in[3];
    if (!b)    b    = (const float*)d_in[4];
    if (!c)    c    = (const float*)d_in[5];

    float* out = (float*)d_out;

    gemv_kernel<<<H, 256>>>(W, ctxv, c);
    transpose_kernel<<<dim3(S / 32, H / 32), dim3(32, 8)>>>(W);
    thr_kernel<<<(S + 255) / 256, 256>>>(u);
    nade_kernel<<<CSZ, TPB>>>(V, b, out, out_size);
}